// round 3
// baseline (speedup 1.0000x reference)
#include <cuda_runtime.h>

// Problem constants (MemoryBank3: memory [1000,128,512] f32)
#define C_CLS   1000
#define N_SLOTS 128
#define D_DIM   512
#define B_MAX   4096

// Scratch (no device allocation allowed -> __device__ globals)
__device__ int   g_cls [B_MAX];          // argmax class per sample
__device__ float g_conf[B_MAX];          // float(batch_confidences[mask[s]])
__device__ int   g_fsrc[B_MAX];          // feature source row = mask[s]
__device__ int   g_rank[B_MAX];          // rank of sample within its class
__device__ int   g_cnt [C_CLS];          // samples per class
__device__ int   g_off [C_CLS + 1];      // exclusive prefix of counts
__device__ int   g_list[B_MAX];          // per-class ordered sample lists
__device__ int   g_slot[C_CLS * N_SLOTS];// final source pointer per output slot

// ---------------------------------------------------------------------------
__global__ void k_init() {
    int t = blockIdx.x * blockDim.x + threadIdx.x;
    if (t < C_CLS) g_cnt[t] = 0;
}

// One block per sample: first-occurrence argmax over C classes + conf cast.
// mask/bconf dtype is sniffed at runtime: selected_mask is arange(B), so as
// int32[] its element 1 is 0 iff the buffer really holds little-endian int64.
__global__ void k_argmax(const float* __restrict__ tgt,
                         const void* __restrict__ bconf,
                         const void* __restrict__ mask, int S) {
    int s = blockIdx.x;
    if (s >= S) return;

    const int* m32 = (const int*)mask;
    bool is64 = (m32[1] == 0);
    int m = is64 ? (int)((const long long*)mask)[s] : m32[s];

    const float* row = tgt + (size_t)m * C_CLS;
    int t = threadIdx.x;
    float best = -3.402823466e38f;
    int bidx = C_CLS;
    for (int k = t; k < C_CLS; k += 128) {
        float v = row[k];
        if (v > best) { best = v; bidx = k; }   // strided ascending -> first-win
    }
    __shared__ float sv[128];
    __shared__ int   si[128];
    sv[t] = best; si[t] = bidx;
    __syncthreads();
    for (int off = 64; off > 0; off >>= 1) {
        if (t < off) {
            if (sv[t + off] > sv[t] ||
                (sv[t + off] == sv[t] && si[t + off] < si[t])) {
                sv[t] = sv[t + off]; si[t] = si[t + off];
            }
        }
        __syncthreads();
    }
    if (t == 0) {
        g_cls [s] = si[0];
        g_conf[s] = is64 ? (float)((const long long*)bconf)[m]
                         : (float)((const int*)bconf)[m];
        g_fsrc[s] = m;
    }
}

// rank[i] = #{j < i : cls[j] == cls[i]}  (stable per-class ordering)
__global__ void k_rank(int S) {
    int i = blockIdx.x * blockDim.x + threadIdx.x;
    if (i >= S) return;
    int c = g_cls[i];
    int r = 0;
    for (int j = 0; j < i; j++) r += (g_cls[j] == c);
    g_rank[i] = r;
    atomicAdd(&g_cnt[c], 1);
}

// Exclusive prefix sum of g_cnt (single block, Hillis-Steele over 1024)
__global__ void k_scan() {
    __shared__ int s[1024];
    int t = threadIdx.x;
    s[t] = (t < C_CLS) ? g_cnt[t] : 0;
    __syncthreads();
    for (int d = 1; d < 1024; d <<= 1) {
        int v = (t >= d) ? s[t - d] : 0;
        __syncthreads();
        s[t] += v;
        __syncthreads();
    }
    if (t < C_CLS) g_off[t + 1] = s[t];
    if (t == 0)    g_off[0] = 0;
}

__global__ void k_scatter(int S) {
    int i = blockIdx.x * blockDim.x + threadIdx.x;
    if (i >= S) return;
    g_list[g_off[g_cls[i]] + g_rank[i]] = i;
}

// One warp per class: simulate sequential updates on (confidence, pointer)
// pairs in SMEM. Stable descending rank-sort; memory never touched here.
__global__ void k_sim(const float* __restrict__ confid) {
    __shared__ float cf [8][N_SLOTS];
    __shared__ int   ptr[8][N_SLOTS];
    int w = threadIdx.x >> 5, lane = threadIdx.x & 31;
    int c = blockIdx.x * 8 + w;
    if (c >= C_CLS) return;
    float* cfs = cf[w];
    int*   ps  = ptr[w];

#pragma unroll
    for (int q = 0; q < 4; q++) {
        int j = lane + 32 * q;
        cfs[j] = confid[c * N_SLOTS + j];
        ps[j]  = j;                         // initially: original memory row j
    }
    __syncwarp();

    int nb = g_cnt[c], base = g_off[c];
    for (int si = 0; si < nb; si++) {
        int   s    = g_list[base + si];
        float conf = g_conf[s];
        if (!(conf > cfs[N_SLOTS - 1])) continue;   // cond = conf > rcf[-1]
        int fslot = N_SLOTS + g_fsrc[s];

        float key[4]; int val[4]; int rk[4];
#pragma unroll
        for (int q = 0; q < 4; q++) {
            int j = lane + 32 * q;
            // ncf: confidences NOT shifted, last slot <- conf
            key[q] = (j < N_SLOTS - 1) ? cfs[j] : conf;
            // shifted memory: drop slot 0, append feature at slot N-1
            val[q] = (j < N_SLOTS - 1) ? ps[j + 1] : fslot;
        }
#pragma unroll
        for (int q = 0; q < 4; q++) {
            int j = lane + 32 * q;
            int r = 0;
            for (int k = 0; k < N_SLOTS; k++) {
                float kk = (k < N_SLOTS - 1) ? cfs[k] : conf;
                // stable descending: earlier if strictly larger, or equal & lower idx
                r += (kk > key[q]) || (kk == key[q] && k < j);
            }
            rk[q] = r;
        }
        __syncwarp();   // all reads of cfs/ps done before scatter
#pragma unroll
        for (int q = 0; q < 4; q++) { cfs[rk[q]] = key[q]; ps[rk[q]] = val[q]; }
        __syncwarp();
    }

#pragma unroll
    for (int q = 0; q < 4; q++) {
        int j = lane + 32 * q;
        g_slot[c * N_SLOTS + j] = ps[j];
    }
}

// One block per output slot: stream 2KB from source (memory row or feature).
__global__ void k_gather(const float* __restrict__ mem,
                         const float* __restrict__ feats,
                         float* __restrict__ out) {
    int b   = blockIdx.x;            // = c*N + n
    int src = g_slot[b];
    int c   = b >> 7;
    const float4* sp;
    if (src < N_SLOTS)
        sp = (const float4*)(mem + ((size_t)(c * N_SLOTS + src)) * D_DIM);
    else
        sp = (const float4*)(feats + (size_t)(src - N_SLOTS) * D_DIM);
    float4* dp = (float4*)(out + (size_t)b * D_DIM);
    dp[threadIdx.x] = sp[threadIdx.x];
}

// ---------------------------------------------------------------------------
extern "C" void kernel_launch(void* const* d_in, const int* in_sizes, int n_in,
                              void* d_out, int out_size) {
    const float* memory = (const float*)d_in[0];
    const float* confid = (const float*)d_in[1];
    const float* feats  = (const float*)d_in[2];
    const float* tgts   = (const float*)d_in[3];
    const void*  bconf  = d_in[4];
    const void*  mask   = d_in[5];
    int S = B_MAX;   // selected_mask has B elements regardless of dtype width

    k_init   <<<1, 1024>>>();
    k_argmax <<<S, 128>>>(tgts, bconf, mask, S);
    k_rank   <<<(S + 255) / 256, 256>>>(S);
    k_scan   <<<1, 1024>>>();
    k_scatter<<<(S + 255) / 256, 256>>>(S);
    k_sim    <<<(C_CLS + 7) / 8, 256>>>(confid);
    k_gather <<<C_CLS * N_SLOTS, 128>>>(memory, feats, (float*)d_out);
}

// round 4
// speedup vs baseline: 1.3833x; 1.3833x over previous
#include <cuda_runtime.h>

// Problem constants (MemoryBank3: memory [1000,128,512] f32)
#define C_CLS   1000
#define N_SLOTS 128
#define D_DIM   512
#define S_B     4096

// Scratch (no device allocation allowed -> __device__ globals)
__device__ int   g_cls [S_B];            // argmax class per sample
__device__ float g_conf[S_B];            // float(batch_confidences[mask[s]])
__device__ int   g_fsrc[S_B];            // feature source row = mask[s]
__device__ int   g_slot[C_CLS * N_SLOTS];// final source pointer per output slot

// ---------------------------------------------------------------------------
// One block per sample: first-occurrence argmax over C classes + conf cast.
// mask/bconf dtype sniffed at runtime: selected_mask is arange(B), so as
// int32[] element 1 is 0 iff the buffer holds little-endian int64.
__global__ void k_argmax(const float* __restrict__ tgt,
                         const void* __restrict__ bconf,
                         const void* __restrict__ mask) {
    int s = blockIdx.x;

    const int* m32 = (const int*)mask;
    bool is64 = (m32[1] == 0);
    int m = is64 ? (int)((const long long*)mask)[s] : m32[s];

    const float* row = tgt + (size_t)m * C_CLS;
    int t = threadIdx.x;
    float best = -3.402823466e38f;
    int bidx = C_CLS;
    for (int k = t; k < C_CLS; k += 128) {
        float v = row[k];
        if (v > best) { best = v; bidx = k; }   // strided ascending -> first-win
    }
    __shared__ float sv[128];
    __shared__ int   si[128];
    sv[t] = best; si[t] = bidx;
    __syncthreads();
    for (int off = 64; off > 0; off >>= 1) {
        if (t < off) {
            if (sv[t + off] > sv[t] ||
                (sv[t + off] == sv[t] && si[t + off] < si[t])) {
                sv[t] = sv[t + off]; si[t] = si[t + off];
            }
        }
        __syncthreads();
    }
    if (t == 0) {
        g_cls [s] = si[0];
        g_conf[s] = is64 ? (float)((const long long*)bconf)[m]
                         : (float)((const int*)bconf)[m];
        g_fsrc[s] = m;
    }
}

// One warp per class. The warp scans g_cls[0..S) in order with ballots to
// find its samples (preserving original sequence), then simulates each
// accepted update on (confidence, pointer) pairs in SMEM via a stable
// descending rank-sort. Memory rows are never moved here.
__global__ void k_sim(const float* __restrict__ confid) {
    __shared__ float cf [8][N_SLOTS];
    __shared__ int   ptr[8][N_SLOTS];
    int w = threadIdx.x >> 5, lane = threadIdx.x & 31;
    int c = blockIdx.x * 8 + w;             // grid sized so c < C_CLS always
    float* cfs = cf[w];
    int*   ps  = ptr[w];

#pragma unroll
    for (int q = 0; q < 4; q++) {
        int j = lane + 32 * q;
        cfs[j] = confid[c * N_SLOTS + j];
        ps[j]  = j;                          // initially: original memory row j
    }
    __syncwarp();

    for (int base = 0; base < S_B; base += 32) {
        int cls = g_cls[base + lane];
        unsigned msk = __ballot_sync(0xffffffffu, cls == c);
        while (msk) {
            int l = __ffs(msk) - 1;
            msk &= msk - 1;
            int   s    = base + l;
            float conf = g_conf[s];          // broadcast load (all lanes same addr)
            if (!(conf > cfs[N_SLOTS - 1])) continue;   // cond = conf > rcf[-1]
            int fslot = N_SLOTS + g_fsrc[s];

            float key[4]; int val[4]; int rk[4];
#pragma unroll
            for (int q = 0; q < 4; q++) {
                int j = lane + 32 * q;
                // ncf: confidences NOT shifted, only last slot <- conf
                key[q] = (j < N_SLOTS - 1) ? cfs[j] : conf;
                // shifted memory: drop slot 0, append feature at slot N-1
                val[q] = (j < N_SLOTS - 1) ? ps[j + 1] : fslot;
            }
#pragma unroll
            for (int q = 0; q < 4; q++) {
                int j = lane + 32 * q;
                int r = 0;
                for (int k = 0; k < N_SLOTS; k++) {
                    float kk = (k < N_SLOTS - 1) ? cfs[k] : conf;
                    // stable descending: earlier if strictly larger, or tie & lower idx
                    r += (kk > key[q]) || (kk == key[q] && k < j);
                }
                rk[q] = r;
            }
            __syncwarp();  // all reads of cfs/ps done before scatter
#pragma unroll
            for (int q = 0; q < 4; q++) { cfs[rk[q]] = key[q]; ps[rk[q]] = val[q]; }
            __syncwarp();
        }
    }

#pragma unroll
    for (int q = 0; q < 4; q++) {
        int j = lane + 32 * q;
        g_slot[c * N_SLOTS + j] = ps[j];
    }
}

// One block per output slot: stream 2KB from source (memory row or feature).
__global__ void k_gather(const float* __restrict__ mem,
                         const float* __restrict__ feats,
                         float* __restrict__ out) {
    int b   = blockIdx.x;                    // = c*N + n
    int src = g_slot[b];
    int c   = b >> 7;
    const float4* sp;
    if (src < N_SLOTS)
        sp = (const float4*)(mem + ((size_t)(c * N_SLOTS + src)) * D_DIM);
    else
        sp = (const float4*)(feats + (size_t)(src - N_SLOTS) * D_DIM);
    float4* dp = (float4*)(out + (size_t)b * D_DIM);
    dp[threadIdx.x] = sp[threadIdx.x];
}

// ---------------------------------------------------------------------------
extern "C" void kernel_launch(void* const* d_in, const int* in_sizes, int n_in,
                              void* d_out, int out_size) {
    const float* memory = (const float*)d_in[0];
    const float* confid = (const float*)d_in[1];
    const float* feats  = (const float*)d_in[2];
    const float* tgts   = (const float*)d_in[3];
    const void*  bconf  = d_in[4];
    const void*  mask   = d_in[5];

    k_argmax <<<S_B, 128>>>(tgts, bconf, mask);
    k_sim    <<<C_CLS / 8, 256>>>(confid);
    k_gather <<<C_CLS * N_SLOTS, 128>>>(memory, feats, (float*)d_out);
}

// round 5
// speedup vs baseline: 1.4193x; 1.0260x over previous
#include <cuda_runtime.h>

// Problem constants (MemoryBank3: memory [1000,128,512] f32)
#define C_CLS   1000
#define N_SLOTS 128
#define D_DIM   512
#define S_B     4096

// Scratch (no device allocation allowed -> __device__ globals)
__device__ int   g_cls [S_B];            // argmax class per sample
__device__ float g_conf[S_B];            // float(batch_confidences[mask[s]])
__device__ int   g_fsrc[S_B];            // feature source row = mask[s]
__device__ int   g_slot[C_CLS * N_SLOTS];// final source pointer per output slot

// ---------------------------------------------------------------------------
// Warp-per-sample argmax: 1000 = 250 float4 per row, 8 vector iters per lane,
// then a 5-step shuffle reduction (max value, tie -> lowest index).
// mask/bconf dtype sniffed at runtime: selected_mask is arange(B), so as
// int32[] element 1 is 0 iff the buffer holds little-endian int64.
__global__ void k_argmax(const float* __restrict__ tgt,
                         const void* __restrict__ bconf,
                         const void* __restrict__ mask) {
    int warp = (blockIdx.x * blockDim.x + threadIdx.x) >> 5;
    int lane = threadIdx.x & 31;
    if (warp >= S_B) return;

    const int* m32 = (const int*)mask;
    bool is64 = (m32[1] == 0);
    int m = is64 ? (int)((const long long*)mask)[warp] : m32[warp];

    const float4* row = (const float4*)(tgt + (size_t)m * C_CLS);
    float best = -3.402823466e38f;
    int   bidx = C_CLS;
#pragma unroll
    for (int it = 0; it < 8; it++) {
        int v4 = lane + 32 * it;             // float4 index, ascending per lane
        if (v4 < 250) {
            float4 v = row[v4];
            int base = v4 * 4;
            if (v.x > best) { best = v.x; bidx = base;     }
            if (v.y > best) { best = v.y; bidx = base + 1; }
            if (v.z > best) { best = v.z; bidx = base + 2; }
            if (v.w > best) { best = v.w; bidx = base + 3; }
        }
    }
    // warp reduce: larger value wins; tie -> lower index (first occurrence)
#pragma unroll
    for (int off = 16; off > 0; off >>= 1) {
        float ov = __shfl_down_sync(0xffffffffu, best, off);
        int   oi = __shfl_down_sync(0xffffffffu, bidx, off);
        if (ov > best || (ov == best && oi < bidx)) { best = ov; bidx = oi; }
    }
    if (lane == 0) {
        g_cls [warp] = bidx;
        g_conf[warp] = is64 ? (float)((const long long*)bconf)[m]
                            : (float)((const int*)bconf)[m];
        g_fsrc[warp] = m;
    }
}

// One warp per class. g_cls is staged into SMEM once per block; each warp
// scans it in order with ballots to find its samples (original sequence
// preserved), then simulates each accepted update on (confidence, pointer)
// pairs via a stable descending rank-sort. Memory rows never move here.
__global__ void k_sim(const float* __restrict__ confid) {
    __shared__ int   scls[S_B];              // 16 KB staged class ids
    __shared__ float cf [8][N_SLOTS];
    __shared__ int   ptr[8][N_SLOTS];
    int w = threadIdx.x >> 5, lane = threadIdx.x & 31;
    int c = blockIdx.x * 8 + w;              // grid sized so c < C_CLS always
    float* cfs = cf[w];
    int*   ps  = ptr[w];

    for (int i = threadIdx.x; i < S_B; i += 256)
        scls[i] = g_cls[i];

#pragma unroll
    for (int q = 0; q < 4; q++) {
        int j = lane + 32 * q;
        cfs[j] = confid[c * N_SLOTS + j];
        ps[j]  = j;                          // initially: original memory row j
    }
    __syncthreads();

    for (int base = 0; base < S_B; base += 32) {
        unsigned msk = __ballot_sync(0xffffffffu, scls[base + lane] == c);
        while (msk) {
            int l = __ffs(msk) - 1;
            msk &= msk - 1;
            int   s    = base + l;
            float conf = g_conf[s];          // broadcast load
            if (!(conf > cfs[N_SLOTS - 1])) continue;   // cond = conf > rcf[-1]
            int fslot = N_SLOTS + g_fsrc[s];

            float key[4]; int val[4]; int rk[4];
#pragma unroll
            for (int q = 0; q < 4; q++) {
                int j = lane + 32 * q;
                // ncf: confidences NOT shifted, only last slot <- conf
                key[q] = (j < N_SLOTS - 1) ? cfs[j] : conf;
                // shifted memory: drop slot 0, append feature at slot N-1
                val[q] = (j < N_SLOTS - 1) ? ps[j + 1] : fslot;
            }
#pragma unroll
            for (int q = 0; q < 4; q++) {
                int j = lane + 32 * q;
                int r = 0;
                for (int k = 0; k < N_SLOTS; k++) {
                    float kk = (k < N_SLOTS - 1) ? cfs[k] : conf;
                    // stable descending: earlier if strictly larger, or tie & lower idx
                    r += (kk > key[q]) || (kk == key[q] && k < j);
                }
                rk[q] = r;
            }
            __syncwarp();  // all reads of cfs/ps done before scatter
#pragma unroll
            for (int q = 0; q < 4; q++) { cfs[rk[q]] = key[q]; ps[rk[q]] = val[q]; }
            __syncwarp();
        }
    }

#pragma unroll
    for (int q = 0; q < 4; q++) {
        int j = lane + 32 * q;
        g_slot[c * N_SLOTS + j] = ps[j];
    }
}

// Two output slots per 256-thread block: stream 2KB per slot (float4 lanes).
__global__ void k_gather(const float* __restrict__ mem,
                         const float* __restrict__ feats,
                         float* __restrict__ out) {
    int slot = blockIdx.x * 2 + (threadIdx.x >> 7);   // = c*N + n
    int t    = threadIdx.x & 127;
    int src  = g_slot[slot];
    int c    = slot >> 7;
    const float4* sp;
    if (src < N_SLOTS)
        sp = (const float4*)(mem + ((size_t)(c * N_SLOTS + src)) * D_DIM);
    else
        sp = (const float4*)(feats + (size_t)(src - N_SLOTS) * D_DIM);
    float4* dp = (float4*)(out + (size_t)slot * D_DIM);
    dp[t] = sp[t];
}

// ---------------------------------------------------------------------------
extern "C" void kernel_launch(void* const* d_in, const int* in_sizes, int n_in,
                              void* d_out, int out_size) {
    const float* memory = (const float*)d_in[0];
    const float* confid = (const float*)d_in[1];
    const float* feats  = (const float*)d_in[2];
    const float* tgts   = (const float*)d_in[3];
    const void*  bconf  = d_in[4];
    const void*  mask   = d_in[5];

    k_argmax <<<S_B / 8, 256>>>(tgts, bconf, mask);        // 8 warps/block
    k_sim    <<<C_CLS / 8, 256>>>(confid);
    k_gather <<<C_CLS * N_SLOTS / 2, 256>>>(memory, feats, (float*)d_out);
}

// round 6
// speedup vs baseline: 1.5538x; 1.0948x over previous
#include <cuda_runtime.h>

// Problem constants (MemoryBank3: memory [1000,128,512] f32)
#define C_CLS   1000
#define N_SLOTS 128
#define D_DIM   512
#define S_B     4096

// Scratch (no device allocation allowed -> __device__ globals)
__device__ int   g_cls [S_B];            // argmax class per sample
__device__ float g_conf[S_B];            // float(batch_confidences[mask[s]])
__device__ int   g_fsrc[S_B];            // feature source row = mask[s]
__device__ int   g_slot[C_CLS * N_SLOTS];// final source pointer per output slot

// ---------------------------------------------------------------------------
// Warp-per-sample argmax: 1000 = 250 float4 per row, 8 vector iters per lane,
// then a 5-step shuffle reduction (max value, tie -> lowest index).
// mask/bconf dtype sniffed at runtime: selected_mask is arange(B), so as
// int32[] element 1 is 0 iff the buffer holds little-endian int64.
__global__ void k_argmax(const float* __restrict__ tgt,
                         const void* __restrict__ bconf,
                         const void* __restrict__ mask) {
    int warp = (blockIdx.x * blockDim.x + threadIdx.x) >> 5;
    int lane = threadIdx.x & 31;
    if (warp >= S_B) return;

    const int* m32 = (const int*)mask;
    bool is64 = (m32[1] == 0);
    int m = is64 ? (int)((const long long*)mask)[warp] : m32[warp];

    const float4* row = (const float4*)(tgt + (size_t)m * C_CLS);
    float best = -3.402823466e38f;
    int   bidx = C_CLS;
#pragma unroll
    for (int it = 0; it < 8; it++) {
        int v4 = lane + 32 * it;             // float4 index, ascending per lane
        if (v4 < 250) {
            float4 v = __ldcs(row + v4);
            int base = v4 * 4;
            if (v.x > best) { best = v.x; bidx = base;     }
            if (v.y > best) { best = v.y; bidx = base + 1; }
            if (v.z > best) { best = v.z; bidx = base + 2; }
            if (v.w > best) { best = v.w; bidx = base + 3; }
        }
    }
    // warp reduce: larger value wins; tie -> lower index (first occurrence)
#pragma unroll
    for (int off = 16; off > 0; off >>= 1) {
        float ov = __shfl_down_sync(0xffffffffu, best, off);
        int   oi = __shfl_down_sync(0xffffffffu, bidx, off);
        if (ov > best || (ov == best && oi < bidx)) { best = ov; bidx = oi; }
    }
    if (lane == 0) {
        g_cls [warp] = bidx;
        g_conf[warp] = is64 ? (float)((const long long*)bconf)[m]
                            : (float)((const int*)bconf)[m];
        g_fsrc[warp] = m;
    }
}

// One warp per class. g_cls is staged into SMEM once per block; each warp
// scans it in order with ballots to find its samples (original sequence
// preserved), then simulates each accepted update on (confidence, pointer)
// pairs via a stable descending rank-sort. Memory rows never move here.
__global__ void k_sim(const float* __restrict__ confid) {
    __shared__ int   scls[S_B];              // 16 KB staged class ids
    __shared__ float cf [8][N_SLOTS];
    __shared__ int   ptr[8][N_SLOTS];
    int w = threadIdx.x >> 5, lane = threadIdx.x & 31;
    int c = blockIdx.x * 8 + w;              // grid sized so c < C_CLS always
    float* cfs = cf[w];
    int*   ps  = ptr[w];

    for (int i = threadIdx.x; i < S_B; i += 256)
        scls[i] = g_cls[i];

#pragma unroll
    for (int q = 0; q < 4; q++) {
        int j = lane + 32 * q;
        cfs[j] = confid[c * N_SLOTS + j];
        ps[j]  = j;                          // initially: original memory row j
    }
    __syncthreads();

    for (int base = 0; base < S_B; base += 32) {
        unsigned msk = __ballot_sync(0xffffffffu, scls[base + lane] == c);
        while (msk) {
            int l = __ffs(msk) - 1;
            msk &= msk - 1;
            int   s    = base + l;
            float conf = g_conf[s];          // broadcast load
            if (!(conf > cfs[N_SLOTS - 1])) continue;   // cond = conf > rcf[-1]
            int fslot = N_SLOTS + g_fsrc[s];

            float key[4]; int val[4]; int rk[4];
#pragma unroll
            for (int q = 0; q < 4; q++) {
                int j = lane + 32 * q;
                // ncf: confidences NOT shifted, only last slot <- conf
                key[q] = (j < N_SLOTS - 1) ? cfs[j] : conf;
                // shifted memory: drop slot 0, append feature at slot N-1
                val[q] = (j < N_SLOTS - 1) ? ps[j + 1] : fslot;
            }
#pragma unroll
            for (int q = 0; q < 4; q++) {
                int j = lane + 32 * q;
                int r = 0;
                for (int k = 0; k < N_SLOTS; k++) {
                    float kk = (k < N_SLOTS - 1) ? cfs[k] : conf;
                    // stable descending: earlier if strictly larger, or tie & lower idx
                    r += (kk > key[q]) || (kk == key[q] && k < j);
                }
                rk[q] = r;
            }
            __syncwarp();  // all reads of cfs/ps done before scatter
#pragma unroll
            for (int q = 0; q < 4; q++) { cfs[rk[q]] = key[q]; ps[rk[q]] = val[q]; }
            __syncwarp();
        }
    }

#pragma unroll
    for (int q = 0; q < 4; q++) {
        int j = lane + 32 * q;
        g_slot[c * N_SLOTS + j] = ps[j];
    }
}

// Warp-per-slot gather: lane i streams float4 {i, i+32, i+64, i+96} of the
// 2KB source row (MLP 4, fully coalesced), evict-first both directions.
__global__ void k_gather(const float* __restrict__ mem,
                         const float* __restrict__ feats,
                         float* __restrict__ out) {
    int slot = blockIdx.x * 8 + (threadIdx.x >> 5);   // = c*N + n
    int lane = threadIdx.x & 31;
    int src  = g_slot[slot];                          // broadcast load
    int c    = slot >> 7;

    const float4* sp = (src < N_SLOTS)
        ? (const float4*)(mem   + ((size_t)(c * N_SLOTS + src)) * D_DIM)
        : (const float4*)(feats + ((size_t)(src - N_SLOTS))     * D_DIM);
    float4* dp = (float4*)(out + (size_t)slot * D_DIM);

    float4 a = __ldcs(sp + lane);
    float4 b = __ldcs(sp + lane + 32);
    float4 d = __ldcs(sp + lane + 64);
    float4 e = __ldcs(sp + lane + 96);
    __stcs(dp + lane,      a);
    __stcs(dp + lane + 32, b);
    __stcs(dp + lane + 64, d);
    __stcs(dp + lane + 96, e);
}

// ---------------------------------------------------------------------------
extern "C" void kernel_launch(void* const* d_in, const int* in_sizes, int n_in,
                              void* d_out, int out_size) {
    const float* memory = (const float*)d_in[0];
    const float* confid = (const float*)d_in[1];
    const float* feats  = (const float*)d_in[2];
    const float* tgts   = (const float*)d_in[3];
    const void*  bconf  = d_in[4];
    const void*  mask   = d_in[5];

    k_argmax <<<S_B / 8, 256>>>(tgts, bconf, mask);         // 8 warps/block
    k_sim    <<<C_CLS / 8, 256>>>(confid);
    k_gather <<<C_CLS * N_SLOTS / 8, 256>>>(memory, feats, (float*)d_out);
}

// round 7
// speedup vs baseline: 2.1395x; 1.3769x over previous
#include <cuda_runtime.h>

// Problem constants (MemoryBank3: memory [1000,128,512] f32)
#define C_CLS   1000
#define N_SLOTS 128
#define D_DIM   512
#define S_B     4096

// Scratch (no device allocation allowed -> __device__ globals)
__device__ int   g_cls [S_B];            // argmax class per sample
__device__ float g_conf[S_B];            // float(batch_confidences[mask[s]])
__device__ int   g_fsrc[S_B];            // feature source row = mask[s]
__device__ int   g_slot[C_CLS * N_SLOTS];// final source pointer per output slot

// ---------------------------------------------------------------------------
// 64 threads (2 warps) per sample: 250 float4 per row, 4 vector iters per
// thread, warp shfl reduce, 2-way smem combine. 8192 warps for latency hiding.
// mask/bconf dtype sniffed at runtime: selected_mask is arange(B), so as
// int32[] element 1 is 0 iff the buffer holds little-endian int64.
__global__ void k_argmax(const float* __restrict__ tgt,
                         const void* __restrict__ bconf,
                         const void* __restrict__ mask) {
    __shared__ float sv[4][2];
    __shared__ int   si[4][2];
    int g    = threadIdx.x >> 6;             // sample group within block (0..3)
    int t64  = threadIdx.x & 63;
    int lane = threadIdx.x & 31;
    int wing = (threadIdx.x >> 5) & 1;       // which warp of the pair
    int s    = blockIdx.x * 4 + g;

    const int* m32 = (const int*)mask;
    bool is64 = (m32[1] == 0);
    int m = is64 ? (int)((const long long*)mask)[s] : m32[s];

    const float4* row = (const float4*)(tgt + (size_t)m * C_CLS);
    float best = -3.402823466e38f;
    int   bidx = C_CLS;
#pragma unroll
    for (int it = 0; it < 4; it++) {
        int v4 = t64 + 64 * it;              // ascending per thread
        if (v4 < 250) {
            float4 v = __ldcs(row + v4);
            int base = v4 * 4;
            if (v.x > best) { best = v.x; bidx = base;     }
            if (v.y > best) { best = v.y; bidx = base + 1; }
            if (v.z > best) { best = v.z; bidx = base + 2; }
            if (v.w > best) { best = v.w; bidx = base + 3; }
        }
    }
    // warp reduce: larger value wins; tie -> lower index (first occurrence)
#pragma unroll
    for (int off = 16; off > 0; off >>= 1) {
        float ov = __shfl_down_sync(0xffffffffu, best, off);
        int   oi = __shfl_down_sync(0xffffffffu, bidx, off);
        if (ov > best || (ov == best && oi < bidx)) { best = ov; bidx = oi; }
    }
    if (lane == 0) { sv[g][wing] = best; si[g][wing] = bidx; }
    __syncthreads();
    if (t64 == 0) {
        float b0 = sv[g][0], b1 = sv[g][1];
        int   i0 = si[g][0], i1 = si[g][1];
        if (b1 > b0 || (b1 == b0 && i1 < i0)) { b0 = b1; i0 = i1; }
        g_cls [s] = i0;
        g_conf[s] = is64 ? (float)((const long long*)bconf)[m]
                         : (float)((const int*)bconf)[m];
        g_fsrc[s] = m;
    }
}

// One warp per class. g_cls staged into SMEM; warp scans it in order with
// ballots (original sequence preserved). First accepted update: general
// stable descending rank-sort (initial confidences are unsorted). After
// that cfs is sorted descending, so each update is a closed-form insertion.
__global__ void k_sim(const float* __restrict__ confid) {
    __shared__ int   scls[S_B];              // 16 KB staged class ids
    __shared__ float cf [8][N_SLOTS];
    __shared__ int   ptr[8][N_SLOTS];
    int w = threadIdx.x >> 5, lane = threadIdx.x & 31;
    int c = blockIdx.x * 8 + w;              // grid sized so c < C_CLS always
    float* cfs = cf[w];
    int*   ps  = ptr[w];

    for (int i = threadIdx.x; i < S_B; i += 256)
        scls[i] = g_cls[i];

#pragma unroll
    for (int q = 0; q < 4; q++) {
        int j = lane + 32 * q;
        cfs[j] = confid[c * N_SLOTS + j];
        ps[j]  = j;                          // initially: original memory row j
    }
    __syncthreads();

    bool sorted = false;                     // cfs sorted desc after 1st update
    for (int base = 0; base < S_B; base += 32) {
        unsigned msk = __ballot_sync(0xffffffffu, scls[base + lane] == c);
        while (msk) {
            int l = __ffs(msk) - 1;
            msk &= msk - 1;
            int   s    = base + l;
            float conf = g_conf[s];          // broadcast load
            if (!(conf > cfs[N_SLOTS - 1])) continue;   // cond = conf > rcf[-1]
            int fslot = N_SLOTS + g_fsrc[s];

            if (sorted) {
                // insertion: p = #{j<N-1 : cfs[j] >= conf} (stable: ties precede)
                int p = 0;
#pragma unroll
                for (int q = 0; q < 4; q++) {
                    int j = lane + 32 * q;
                    unsigned b = __ballot_sync(0xffffffffu,
                                               j < N_SLOTS - 1 && cfs[j] >= conf);
                    p += __popc(b);
                }
                float key[4]; int val[4];
#pragma unroll
                for (int q = 0; q < 4; q++) {
                    int j = lane + 32 * q;
                    key[q] = (j < p) ? cfs[j]    : (j == p ? conf  : cfs[j - 1]);
                    val[q] = (j < p) ? ps[j + 1] : (j == p ? fslot : ps[j]);
                }
                __syncwarp();                // all reads done before writes
#pragma unroll
                for (int q = 0; q < 4; q++) {
                    int j = lane + 32 * q;
                    cfs[j] = key[q]; ps[j] = val[q];
                }
                __syncwarp();
            } else {
                // general stable descending rank-sort (unsorted initial state)
                float key[4]; int val[4]; int rk[4];
#pragma unroll
                for (int q = 0; q < 4; q++) {
                    int j = lane + 32 * q;
                    // ncf: confidences NOT shifted, only last slot <- conf
                    key[q] = (j < N_SLOTS - 1) ? cfs[j] : conf;
                    // shifted memory: drop slot 0, append feature at slot N-1
                    val[q] = (j < N_SLOTS - 1) ? ps[j + 1] : fslot;
                }
#pragma unroll
                for (int q = 0; q < 4; q++) {
                    int j = lane + 32 * q;
                    int r = 0;
                    for (int k = 0; k < N_SLOTS; k++) {
                        float kk = (k < N_SLOTS - 1) ? cfs[k] : conf;
                        r += (kk > key[q]) || (kk == key[q] && k < j);
                    }
                    rk[q] = r;
                }
                __syncwarp();
#pragma unroll
                for (int q = 0; q < 4; q++) { cfs[rk[q]] = key[q]; ps[rk[q]] = val[q]; }
                __syncwarp();
                sorted = true;
            }
        }
    }

#pragma unroll
    for (int q = 0; q < 4; q++) {
        int j = lane + 32 * q;
        g_slot[c * N_SLOTS + j] = ps[j];
    }
}

// Two slots per warp: 8 independent float4 loads in flight per thread pair
// of rows (MLP 8 front-batched), evict-first streaming both directions.
__global__ void k_gather(const float* __restrict__ mem,
                         const float* __restrict__ feats,
                         float* __restrict__ out) {
    int warp  = blockIdx.x * 8 + (threadIdx.x >> 5);
    int lane  = threadIdx.x & 31;
    int slot0 = warp * 2;
    int slot1 = slot0 + 1;

    int src0 = g_slot[slot0];
    int src1 = g_slot[slot1];
    int c0   = slot0 >> 7;
    int c1   = slot1 >> 7;

    const float4* sp0 = (src0 < N_SLOTS)
        ? (const float4*)(mem   + ((size_t)(c0 * N_SLOTS + src0)) * D_DIM)
        : (const float4*)(feats + ((size_t)(src0 - N_SLOTS))      * D_DIM);
    const float4* sp1 = (src1 < N_SLOTS)
        ? (const float4*)(mem   + ((size_t)(c1 * N_SLOTS + src1)) * D_DIM)
        : (const float4*)(feats + ((size_t)(src1 - N_SLOTS))      * D_DIM);
    float4* dp0 = (float4*)(out + (size_t)slot0 * D_DIM);
    float4* dp1 = (float4*)(out + (size_t)slot1 * D_DIM);

    float4 a0 = __ldcs(sp0 + lane);
    float4 a1 = __ldcs(sp0 + lane + 32);
    float4 a2 = __ldcs(sp0 + lane + 64);
    float4 a3 = __ldcs(sp0 + lane + 96);
    float4 b0 = __ldcs(sp1 + lane);
    float4 b1 = __ldcs(sp1 + lane + 32);
    float4 b2 = __ldcs(sp1 + lane + 64);
    float4 b3 = __ldcs(sp1 + lane + 96);
    __stcs(dp0 + lane,      a0);
    __stcs(dp0 + lane + 32, a1);
    __stcs(dp0 + lane + 64, a2);
    __stcs(dp0 + lane + 96, a3);
    __stcs(dp1 + lane,      b0);
    __stcs(dp1 + lane + 32, b1);
    __stcs(dp1 + lane + 64, b2);
    __stcs(dp1 + lane + 96, b3);
}

// ---------------------------------------------------------------------------
extern "C" void kernel_launch(void* const* d_in, const int* in_sizes, int n_in,
                              void* d_out, int out_size) {
    const float* memory = (const float*)d_in[0];
    const float* confid = (const float*)d_in[1];
    const float* feats  = (const float*)d_in[2];
    const float* tgts   = (const float*)d_in[3];
    const void*  bconf  = d_in[4];
    const void*  mask   = d_in[5];

    k_argmax <<<S_B / 4, 256>>>(tgts, bconf, mask);          // 64 thr/sample
    k_sim    <<<C_CLS / 8, 256>>>(confid);
    k_gather <<<C_CLS * N_SLOTS / 16, 256>>>(memory, feats, (float*)d_out);
}